// round 10
// baseline (speedup 1.0000x reference)
#include <cuda_runtime.h>
#include <cuda_bf16.h>
#include <cstdint>

#define BT 8
#define SEQ 4096
#define NST 256
#define DIN 256
#define DOUT 256
#define M_TOT (BT*SEQ)          // 32768
#define CHUNK 64
#define NCHUNK (SEQ/CHUNK)      // 64

typedef unsigned long long u64;
typedef __nv_bfloat16 bf16;

// ---------------- device scratch ----------------
__device__ float g_Ar[NST], g_Ai[NST];
__device__ float g_ALr[NST], g_ALi[NST];
__device__ float g_wr[NST], g_wi[NST];
__device__ bf16  g_xh[(size_t)M_TOT*DIN], g_xl[(size_t)M_TOT*DIN];
__device__ bf16  g_W1h[512*DIN], g_W1l[512*DIN];   // [Bbar_r; Bbar_i]
__device__ bf16  g_W2h[DOUT*512], g_W2l[DOUT*512]; // [Cr | -Ci]
__device__ float g_u[(size_t)M_TOT*512];      // u: [:,0:256]=real  [:,256:512]=imag
__device__ bf16  g_hh[(size_t)M_TOT*512];     // h hi: [hr | hi_part]
__device__ bf16  g_hl[(size_t)M_TOT*512];     // h lo
__device__ float g_cr[BT*NCHUNK*NST], g_ci[BT*NCHUNK*NST];
__device__ float g_pr[BT*NCHUNK*NST], g_pi[BT*NCHUNK*NST];

__device__ __forceinline__ void bsplit(float v, bf16& h, bf16& l) {
    h = __float2bfloat16(v);
    l = __float2bfloat16(v - __bfloat162float(h));
}

// mma.sync m16n8k16 row.col bf16 -> f32 accumulate
__device__ __forceinline__ void hmma(float* d, const uint32_t* a, const uint32_t* b) {
    asm volatile(
        "mma.sync.aligned.m16n8k16.row.col.f32.bf16.bf16.f32 "
        "{%0,%1,%2,%3}, {%4,%5,%6,%7}, {%8,%9}, {%0,%1,%2,%3};"
        : "+f"(d[0]), "+f"(d[1]), "+f"(d[2]), "+f"(d[3])
        : "r"(a[0]), "r"(a[1]), "r"(a[2]), "r"(a[3]), "r"(b[0]), "r"(b[1]));
}
__device__ __forceinline__ void ldsm_x4(uint32_t* r, uint32_t addr) {
    asm volatile("ldmatrix.sync.aligned.m8n8.x4.shared.b16 {%0,%1,%2,%3}, [%4];"
        : "=r"(r[0]), "=r"(r[1]), "=r"(r[2]), "=r"(r[3]) : "r"(addr));
}
__device__ __forceinline__ void cpa16(uint32_t saddr, const void* g) {
    asm volatile("cp.async.cg.shared.global [%0], [%1], 16;" :: "r"(saddr), "l"(g));
}
__device__ __forceinline__ uint32_t smem_u32(const void* p) {
    uint32_t a;
    asm("{ .reg .u64 t; cvta.to.shared.u64 t, %1; cvt.u32.u64 %0, t; }" : "=r"(a) : "l"(p));
    return a;
}
// swizzled byte offset inside a R x 64 bf16 tile
__device__ __forceinline__ uint32_t swz(int row, int g8) {
    return (uint32_t)(row * 64 + ((g8 ^ (row & 7)) * 8)) * 2;
}

// ---------------- setup: per-n scalars only ----------------
__global__ void k_setup(const float* __restrict__ llr, const float* __restrict__ lim,
                        const float* __restrict__ ldt) {
    int n = threadIdx.x;
    float lr = -expf(llr[n]);
    float li = lim[n];
    float dt = expf(ldt[n]);
    dt = fminf(fmaxf(dt, 0.005f), 0.1f);
    float dr = 1.f - 0.5f * dt * lr;
    float di = -0.5f * dt * li;
    float nr = 1.f + 0.5f * dt * lr;
    float ni = 0.5f * dt * li;
    float inv = 1.f / (dr*dr + di*di);
    float Ar = (nr*dr + ni*di) * inv;
    float Ai = (ni*dr - nr*di) * inv;
    g_Ar[n] = Ar; g_Ai[n] = Ai;
    g_wr[n] = dt * dr * inv;
    g_wi[n] = -dt * di * inv;
    float pr = 1.f, pi = 0.f;
    for (int j = 0; j < CHUNK; j++) {
        float t = pr*Ar - pi*Ai;
        pi = pr*Ai + pi*Ar;
        pr = t;
    }
    g_ALr[n] = pr; g_ALi[n] = pi;
}

__global__ __launch_bounds__(256) void k_w1(const float* __restrict__ Bm) {
    int idx = blockIdx.x * blockDim.x + threadIdx.x;   // over 256*256
    int n = idx >> 8, k = idx & 255;
    float b = Bm[idx];
    bsplit(g_wr[n] * b, g_W1h[idx],             g_W1l[idx]);
    bsplit(g_wi[n] * b, g_W1h[(256+n)*DIN + k], g_W1l[(256+n)*DIN + k]);
}

__global__ void k_w2(const float* __restrict__ Cr, const float* __restrict__ Ci) {
    int idx = blockIdx.x * blockDim.x + threadIdx.x;   // over 256*512
    int d = idx >> 9, k = idx & 511;
    float v = (k < 256) ? Cr[d*256 + k] : -Ci[d*256 + (k - 256)];
    bsplit(v, g_W2h[idx], g_W2l[idx]);
}

__global__ __launch_bounds__(256) void k_cvt(const float* __restrict__ x) {
    size_t i = (size_t)(blockIdx.x * blockDim.x + threadIdx.x) * 4;
    float4 v = *(const float4*)&x[i];
    bf16 h0,l0,h1,l1,h2,l2,h3,l3;
    bsplit(v.x,h0,l0); bsplit(v.y,h1,l1); bsplit(v.z,h2,l2); bsplit(v.w,h3,l3);
    __nv_bfloat162 hh0={h0,h1}, hh1={h2,h3}, ll0={l0,l1}, ll1={l2,l3};
    *(uint2*)&g_xh[i] = make_uint2(*(uint32_t*)&hh0, *(uint32_t*)&hh1);
    *(uint2*)&g_xl[i] = make_uint2(*(uint32_t*)&ll0, *(uint32_t*)&ll1);
}

// ---------------- HMMA GEMM, M-tile = MF*64, N-tile 128, swizzled smem ----------------
template<int MF>
__global__ __launch_bounds__(256, 1) void k_gemm(
    const bf16* __restrict__ Ah, const bf16* __restrict__ Al, int lda,
    const bf16* __restrict__ Wh, const bf16* __restrict__ Wl,
    float* __restrict__ out, int ldc, int Kdim)
{
    constexpr int MT = MF * 64;
    constexpr int A_EL = MT * 64;
    constexpr int W_EL = 128 * 64;
    constexpr int STAGE_EL = 2 * A_EL + 2 * W_EL;

    extern __shared__ bf16 smem[];
    const uint32_t sb = smem_u32(smem);
    const int tid = threadIdx.x;
    const int wid = tid >> 5, lane = tid & 31;
    const int m0 = blockIdx.y * MT;
    const int n0 = blockIdx.x * 128;
    const int wm = wid >> 1;
    const int wn = wid & 1;
    const int g  = lane >> 2;
    const int q4 = lane & 3;

    float acc[MF][8][4];
    #pragma unroll
    for (int i = 0; i < MF; i++)
        #pragma unroll
        for (int j = 0; j < 8; j++)
            #pragma unroll
            for (int r = 0; r < 4; r++) acc[i][j][r] = 0.f;

    const int nchunks = Kdim / 64;

    const int a_row = (lane & 7) + ((lane >> 3) & 1) * 8;
    const int a_g8  = lane >> 4;
    const int w_row = (lane & 7) + ((lane >> 4) & 1) * 8;
    const int w_g8  = (lane >> 3) & 1;

    auto prefetch = [&](int stage, int ch) {
        const int k0 = ch * 64;
        const uint32_t s0 = sb + (uint32_t)stage * STAGE_EL * 2;
        const uint32_t sAh = s0, sAl = s0 + A_EL*2;
        const uint32_t sWh = s0 + 2*A_EL*2, sWl = s0 + 2*A_EL*2 + W_EL*2;
        #pragma unroll
        for (int i = 0; i < MF*2; i++) {
            int v = tid + i * 256;
            int row = v >> 3, q = v & 7;
            uint32_t so = swz(row, q);
            const size_t ga = (size_t)(m0 + row) * lda + k0 + q * 8;
            cpa16(sAh + so, Ah + ga);
            cpa16(sAl + so, Al + ga);
        }
        #pragma unroll
        for (int i = 0; i < 4; i++) {
            int v = tid + i * 256;
            int row = v >> 3, q = v & 7;
            uint32_t so = swz(row, q);
            const size_t gw = (size_t)(n0 + row) * Kdim + k0 + q * 8;
            cpa16(sWh + so, Wh + gw);
            cpa16(sWl + so, Wl + gw);
        }
        asm volatile("cp.async.commit_group;");
    };

    prefetch(0, 0);

    for (int ch = 0; ch < nchunks; ch++) {
        const int st = ch & 1;
        asm volatile("cp.async.wait_group 0;");
        __syncthreads();
        if (ch + 1 < nchunks) prefetch(st ^ 1, ch + 1);

        const uint32_t s0 = sb + (uint32_t)st * STAGE_EL * 2;
        const uint32_t sAh = s0, sAl = s0 + A_EL*2;
        const uint32_t sWh = s0 + 2*A_EL*2, sWl = s0 + 2*A_EL*2 + W_EL*2;

        #pragma unroll
        for (int ks = 0; ks < 4; ks++) {
            uint32_t bh[8][2], bl[8][2];
            #pragma unroll
            for (int p = 0; p < 4; p++) {
                int nrow = wn*64 + p*16 + w_row;
                uint32_t off = swz(nrow, ks*2 + w_g8);
                uint32_t t[4];
                ldsm_x4(t, sWh + off);
                bh[2*p][0]=t[0]; bh[2*p][1]=t[1]; bh[2*p+1][0]=t[2]; bh[2*p+1][1]=t[3];
                ldsm_x4(t, sWl + off);
                bl[2*p][0]=t[0]; bl[2*p][1]=t[1]; bl[2*p+1][0]=t[2]; bl[2*p+1][1]=t[3];
            }
            uint32_t ah[MF][4], al[MF][4];
            #pragma unroll
            for (int mf = 0; mf < MF; mf++) {
                int row = wm*(MF*16) + mf*16 + a_row;
                uint32_t off = swz(row, ks*2 + a_g8);
                ldsm_x4(ah[mf], sAh + off);
                ldsm_x4(al[mf], sAl + off);
            }
            // pass-major ordering: all HMMAs within a pass hit distinct
            // accumulators; each acc is revisited 32 HMMAs later -> no
            // dependent back-to-back HMMA chains.
            #pragma unroll
            for (int nf = 0; nf < 8; nf++)
                #pragma unroll
                for (int mf = 0; mf < MF; mf++)
                    hmma(acc[mf][nf], ah[mf], bh[nf]);
            #pragma unroll
            for (int nf = 0; nf < 8; nf++)
                #pragma unroll
                for (int mf = 0; mf < MF; mf++)
                    hmma(acc[mf][nf], ah[mf], bl[nf]);
            #pragma unroll
            for (int nf = 0; nf < 8; nf++)
                #pragma unroll
                for (int mf = 0; mf < MF; mf++)
                    hmma(acc[mf][nf], al[mf], bh[nf]);
        }
    }

    #pragma unroll
    for (int mf = 0; mf < MF; mf++) {
        int row = m0 + wm*(MF*16) + mf*16 + g;
        #pragma unroll
        for (int nf = 0; nf < 8; nf++) {
            int col = n0 + wn*64 + nf*8 + q4*2;
            *(float2*)&out[(size_t)row * ldc + col]       = make_float2(acc[mf][nf][0], acc[mf][nf][1]);
            *(float2*)&out[(size_t)(row + 8) * ldc + col] = make_float2(acc[mf][nf][2], acc[mf][nf][3]);
        }
    }
}

#define GEMM_MF 4
#define GEMM_SMEM ((2*(2*(GEMM_MF*64*64) + 2*(128*64)))*2)

// ---------------- scan pass 1: chunk end states only ----------------
__global__ __launch_bounds__(256) void k_scan1() {
    const int b = blockIdx.x / NCHUNK, c = blockIdx.x % NCHUNK;
    const int n = threadIdx.x;
    const float Ar = g_Ar[n], Ai = g_Ai[n];
    size_t base = ((size_t)b*SEQ + (size_t)c*CHUNK) * 512 + n;
    float hr = 0.f, hi = 0.f;
    #pragma unroll 8
    for (int j = 0; j < CHUNK; j++) {
        float ur = g_u[base], ui = g_u[base + 256];
        float nhr = fmaf(Ar, hr, fmaf(-Ai, hi, ur));
        float nhi = fmaf(Ar, hi, fmaf( Ai, hr, ui));
        hr = nhr; hi = nhi;
        base += 512;
    }
    g_cr[(b*NCHUNK + c)*NST + n] = hr;
    g_ci[(b*NCHUNK + c)*NST + n] = hi;
}

// ---------------- scan pass 2: cross-chunk prefix ----------------
__global__ __launch_bounds__(256) void k_scan2() {
    const int b = blockIdx.x;
    const int n = threadIdx.x;
    const float Ar = g_ALr[n], Ai = g_ALi[n];
    float hr = 0.f, hi = 0.f;
    for (int cb = 0; cb < 4; cb++) {
        float cr[16], ci[16];
        #pragma unroll
        for (int i = 0; i < 16; i++) {
            int idx = (b*NCHUNK + cb*16 + i)*NST + n;
            cr[i] = g_cr[idx]; ci[i] = g_ci[idx];
        }
        #pragma unroll
        for (int i = 0; i < 16; i++) {
            int idx = (b*NCHUNK + cb*16 + i)*NST + n;
            g_pr[idx] = hr; g_pi[idx] = hi;
            float nhr = fmaf(Ar, hr, fmaf(-Ai, hi, cr[i]));
            float nhi = fmaf(Ar, hi, fmaf( Ai, hr, ci[i]));
            hr = nhr; hi = nhi;
        }
    }
}

// ---------------- scan pass 3: full scan with carry, emit h as bf16 hi/lo ----------------
__global__ __launch_bounds__(256) void k_scan3() {
    const int b = blockIdx.x / NCHUNK, c = blockIdx.x % NCHUNK;
    const int n = threadIdx.x;
    const float Ar = g_Ar[n], Ai = g_Ai[n];
    float hr = g_pr[(b*NCHUNK + c)*NST + n];
    float hi = g_pi[(b*NCHUNK + c)*NST + n];
    size_t base = ((size_t)b*SEQ + (size_t)c*CHUNK) * 512 + n;
    #pragma unroll 8
    for (int j = 0; j < CHUNK; j++) {
        float ur = g_u[base], ui = g_u[base + 256];
        float nhr = fmaf(Ar, hr, fmaf(-Ai, hi, ur));
        float nhi = fmaf(Ar, hi, fmaf( Ai, hr, ui));
        hr = nhr; hi = nhi;
        bsplit(hr, g_hh[base],       g_hl[base]);
        bsplit(hi, g_hh[base + 256], g_hl[base + 256]);
        base += 512;
    }
}

// ---------------- launch ----------------
extern "C" void kernel_launch(void* const* d_in, const int* in_sizes, int n_in,
                              void* d_out, int out_size) {
    const float* x   = (const float*)d_in[0];
    const float* llr = (const float*)d_in[1];
    const float* lim = (const float*)d_in[2];
    const float* ldt = (const float*)d_in[3];
    const float* Bm  = (const float*)d_in[4];
    const float* Cr  = (const float*)d_in[5];
    const float* Ci  = (const float*)d_in[6];
    float* out = (float*)d_out;

    cudaFuncSetAttribute(k_gemm<GEMM_MF>, cudaFuncAttributeMaxDynamicSharedMemorySize, GEMM_SMEM);

    bf16 *xh, *xl, *w1h, *w1l, *w2h, *w2l, *hh, *hl;
    float *u;
    cudaGetSymbolAddress((void**)&xh, g_xh);
    cudaGetSymbolAddress((void**)&xl, g_xl);
    cudaGetSymbolAddress((void**)&w1h, g_W1h);
    cudaGetSymbolAddress((void**)&w1l, g_W1l);
    cudaGetSymbolAddress((void**)&w2h, g_W2h);
    cudaGetSymbolAddress((void**)&w2l, g_W2l);
    cudaGetSymbolAddress((void**)&hh, g_hh);
    cudaGetSymbolAddress((void**)&hl, g_hl);
    cudaGetSymbolAddress((void**)&u, g_u);

    k_setup<<<1, 256>>>(llr, lim, ldt);
    k_w1<<<(256*256)/256, 256>>>(Bm);
    k_w2<<<(256*512)/256, 256>>>(Cr, Ci);
    k_cvt<<<(M_TOT*DIN/4)/256, 256>>>(x);
    // GEMM1: u[M,512] = x @ [Bbar_r;Bbar_i]^T
    k_gemm<GEMM_MF><<<dim3(512/128, M_TOT/(GEMM_MF*64)), 256, GEMM_SMEM>>>(xh, xl, DIN, w1h, w1l, u, 512, DIN);
    k_scan1<<<BT*NCHUNK, 256>>>();
    k_scan2<<<BT, 256>>>();
    k_scan3<<<BT*NCHUNK, 256>>>();
    // GEMM2: out[M,256] = [hr|hi] @ [Cr|-Ci]^T
    k_gemm<GEMM_MF><<<dim3(DOUT/128, M_TOT/(GEMM_MF*64)), 256, GEMM_SMEM>>>(hh, hl, 512, w2h, w2l, out, DOUT, 512);
}

// round 11
// speedup vs baseline: 1.0001x; 1.0001x over previous
#include <cuda_runtime.h>
#include <cuda_bf16.h>
#include <cstdint>

#define BT 8
#define SEQ 4096
#define NST 256
#define DIN 256
#define DOUT 256
#define M_TOT (BT*SEQ)          // 32768
#define CHUNK 64
#define NCHUNK (SEQ/CHUNK)      // 64

typedef unsigned long long u64;
typedef __nv_bfloat16 bf16;

// ---------------- device scratch ----------------
__device__ float g_Ar[NST], g_Ai[NST];
__device__ float g_ALr[NST], g_ALi[NST];
__device__ float g_wr[NST], g_wi[NST];
__device__ bf16  g_xh[(size_t)M_TOT*DIN], g_xl[(size_t)M_TOT*DIN];
__device__ bf16  g_W1h[512*DIN], g_W1l[512*DIN];   // [Bbar_r; Bbar_i]
__device__ bf16  g_W2h[DOUT*512], g_W2l[DOUT*512]; // [Cr | -Ci]
__device__ float g_u[(size_t)M_TOT*512];      // u: [:,0:256]=real  [:,256:512]=imag
__device__ bf16  g_hh[(size_t)M_TOT*512];     // h hi: [hr | hi_part]
__device__ bf16  g_hl[(size_t)M_TOT*512];     // h lo
__device__ float g_cr[BT*NCHUNK*NST], g_ci[BT*NCHUNK*NST];
__device__ float g_pr[BT*NCHUNK*NST], g_pi[BT*NCHUNK*NST];

__device__ __forceinline__ void bsplit(float v, bf16& h, bf16& l) {
    h = __float2bfloat16(v);
    l = __float2bfloat16(v - __bfloat162float(h));
}

// mma.sync m16n8k16 row.col bf16 -> f32 accumulate
__device__ __forceinline__ void hmma(float* d, const uint32_t* a, const uint32_t* b) {
    asm volatile(
        "mma.sync.aligned.m16n8k16.row.col.f32.bf16.bf16.f32 "
        "{%0,%1,%2,%3}, {%4,%5,%6,%7}, {%8,%9}, {%0,%1,%2,%3};"
        : "+f"(d[0]), "+f"(d[1]), "+f"(d[2]), "+f"(d[3])
        : "r"(a[0]), "r"(a[1]), "r"(a[2]), "r"(a[3]), "r"(b[0]), "r"(b[1]));
}
__device__ __forceinline__ void ldsm_x4(uint32_t* r, uint32_t addr) {
    asm volatile("ldmatrix.sync.aligned.m8n8.x4.shared.b16 {%0,%1,%2,%3}, [%4];"
        : "=r"(r[0]), "=r"(r[1]), "=r"(r[2]), "=r"(r[3]) : "r"(addr));
}
__device__ __forceinline__ void cpa16(uint32_t saddr, const void* g) {
    asm volatile("cp.async.cg.shared.global [%0], [%1], 16;" :: "r"(saddr), "l"(g));
}
__device__ __forceinline__ uint32_t smem_u32(const void* p) {
    uint32_t a;
    asm("{ .reg .u64 t; cvta.to.shared.u64 t, %1; cvt.u32.u64 %0, t; }" : "=r"(a) : "l"(p));
    return a;
}
// swizzled byte offset inside a R x 64 bf16 tile
__device__ __forceinline__ uint32_t swz(int row, int g8) {
    return (uint32_t)(row * 64 + ((g8 ^ (row & 7)) * 8)) * 2;
}

// ---------------- setup: per-n scalars only ----------------
__global__ void k_setup(const float* __restrict__ llr, const float* __restrict__ lim,
                        const float* __restrict__ ldt) {
    int n = threadIdx.x;
    float lr = -expf(llr[n]);
    float li = lim[n];
    float dt = expf(ldt[n]);
    dt = fminf(fmaxf(dt, 0.005f), 0.1f);
    float dr = 1.f - 0.5f * dt * lr;
    float di = -0.5f * dt * li;
    float nr = 1.f + 0.5f * dt * lr;
    float ni = 0.5f * dt * li;
    float inv = 1.f / (dr*dr + di*di);
    float Ar = (nr*dr + ni*di) * inv;
    float Ai = (ni*dr - nr*di) * inv;
    g_Ar[n] = Ar; g_Ai[n] = Ai;
    g_wr[n] = dt * dr * inv;
    g_wi[n] = -dt * di * inv;
    float pr = 1.f, pi = 0.f;
    for (int j = 0; j < CHUNK; j++) {
        float t = pr*Ar - pi*Ai;
        pi = pr*Ai + pi*Ar;
        pr = t;
    }
    g_ALr[n] = pr; g_ALi[n] = pi;
}

__global__ __launch_bounds__(256) void k_w1(const float* __restrict__ Bm) {
    int idx = blockIdx.x * blockDim.x + threadIdx.x;   // over 256*256
    int n = idx >> 8, k = idx & 255;
    float b = Bm[idx];
    bsplit(g_wr[n] * b, g_W1h[idx],             g_W1l[idx]);
    bsplit(g_wi[n] * b, g_W1h[(256+n)*DIN + k], g_W1l[(256+n)*DIN + k]);
}

__global__ void k_w2(const float* __restrict__ Cr, const float* __restrict__ Ci) {
    int idx = blockIdx.x * blockDim.x + threadIdx.x;   // over 256*512
    int d = idx >> 9, k = idx & 511;
    float v = (k < 256) ? Cr[d*256 + k] : -Ci[d*256 + (k - 256)];
    bsplit(v, g_W2h[idx], g_W2l[idx]);
}

__global__ __launch_bounds__(256) void k_cvt(const float* __restrict__ x) {
    size_t i = (size_t)(blockIdx.x * blockDim.x + threadIdx.x) * 4;
    float4 v = *(const float4*)&x[i];
    bf16 h0,l0,h1,l1,h2,l2,h3,l3;
    bsplit(v.x,h0,l0); bsplit(v.y,h1,l1); bsplit(v.z,h2,l2); bsplit(v.w,h3,l3);
    __nv_bfloat162 hh0={h0,h1}, hh1={h2,h3}, ll0={l0,l1}, ll1={l2,l3};
    *(uint2*)&g_xh[i] = make_uint2(*(uint32_t*)&hh0, *(uint32_t*)&hh1);
    *(uint2*)&g_xl[i] = make_uint2(*(uint32_t*)&ll0, *(uint32_t*)&ll1);
}

// ---------------- HMMA GEMM: 256x128 tile, 512 threads (16 warps) ----------------
// 16 warps: wm = wid>>1 in [0,8) -> 32-row strip; wn = wid&1 -> 64 cols.
#define MT 256
#define A_EL (MT*64)
#define W_EL (128*64)
#define STAGE_EL (2*A_EL + 2*W_EL)
#define GEMM_SMEM (2*STAGE_EL*2)

__global__ __launch_bounds__(512, 1) void k_gemm(
    const bf16* __restrict__ Ah, const bf16* __restrict__ Al, int lda,
    const bf16* __restrict__ Wh, const bf16* __restrict__ Wl,
    float* __restrict__ out, int ldc, int Kdim)
{
    extern __shared__ bf16 smem[];
    const uint32_t sb = smem_u32(smem);
    const int tid = threadIdx.x;
    const int wid = tid >> 5, lane = tid & 31;
    const int m0 = blockIdx.y * MT;
    const int n0 = blockIdx.x * 128;
    const int wm = wid >> 1;            // 0..7, 32 rows each
    const int wn = wid & 1;             // 0..1, 64 cols each
    const int g  = lane >> 2;
    const int q4 = lane & 3;

    float acc[2][8][4];
    #pragma unroll
    for (int i = 0; i < 2; i++)
        #pragma unroll
        for (int j = 0; j < 8; j++)
            #pragma unroll
            for (int r = 0; r < 4; r++) acc[i][j][r] = 0.f;

    const int nchunks = Kdim / 64;

    const int a_row = (lane & 7) + ((lane >> 3) & 1) * 8;
    const int a_g8  = lane >> 4;
    const int w_row = (lane & 7) + ((lane >> 4) & 1) * 8;
    const int w_g8  = (lane >> 3) & 1;

    auto prefetch = [&](int stage, int ch) {
        const int k0 = ch * 64;
        const uint32_t s0 = sb + (uint32_t)stage * STAGE_EL * 2;
        const uint32_t sAh = s0, sAl = s0 + A_EL*2;
        const uint32_t sWh = s0 + 2*A_EL*2, sWl = s0 + 2*A_EL*2 + W_EL*2;
        #pragma unroll
        for (int i = 0; i < 4; i++) {           // A: 2048 16B vecs, hi+lo
            int v = tid + i * 512;
            int row = v >> 3, q = v & 7;
            uint32_t so = swz(row, q);
            const size_t ga = (size_t)(m0 + row) * lda + k0 + q * 8;
            cpa16(sAh + so, Ah + ga);
            cpa16(sAl + so, Al + ga);
        }
        #pragma unroll
        for (int i = 0; i < 2; i++) {           // W: 1024 vecs, hi+lo
            int v = tid + i * 512;
            int row = v >> 3, q = v & 7;
            uint32_t so = swz(row, q);
            const size_t gw = (size_t)(n0 + row) * Kdim + k0 + q * 8;
            cpa16(sWh + so, Wh + gw);
            cpa16(sWl + so, Wl + gw);
        }
        asm volatile("cp.async.commit_group;");
    };

    prefetch(0, 0);

    for (int ch = 0; ch < nchunks; ch++) {
        const int st = ch & 1;
        asm volatile("cp.async.wait_group 0;");
        __syncthreads();
        if (ch + 1 < nchunks) prefetch(st ^ 1, ch + 1);

        const uint32_t s0 = sb + (uint32_t)st * STAGE_EL * 2;
        const uint32_t sAh = s0, sAl = s0 + A_EL*2;
        const uint32_t sWh = s0 + 2*A_EL*2, sWl = s0 + 2*A_EL*2 + W_EL*2;

        #pragma unroll
        for (int ks = 0; ks < 4; ks++) {
            uint32_t ah[2][4], al[2][4];
            #pragma unroll
            for (int mf = 0; mf < 2; mf++) {
                int row = wm*32 + mf*16 + a_row;
                uint32_t off = swz(row, ks*2 + a_g8);
                ldsm_x4(ah[mf], sAh + off);
                ldsm_x4(al[mf], sAl + off);
            }
            #pragma unroll
            for (int p = 0; p < 4; p++) {
                int nrow = wn*64 + p*16 + w_row;
                uint32_t off = swz(nrow, ks*2 + w_g8);
                uint32_t bh[4], bl[4];              // 2 n-frags hi + lo
                ldsm_x4(bh, sWh + off);
                ldsm_x4(bl, sWl + off);
                #pragma unroll
                for (int j = 0; j < 2; j++)
                    #pragma unroll
                    for (int mf = 0; mf < 2; mf++)
                        hmma(acc[mf][2*p+j], ah[mf], bh + 2*j);
                #pragma unroll
                for (int j = 0; j < 2; j++)
                    #pragma unroll
                    for (int mf = 0; mf < 2; mf++)
                        hmma(acc[mf][2*p+j], ah[mf], bl + 2*j);
                #pragma unroll
                for (int j = 0; j < 2; j++)
                    #pragma unroll
                    for (int mf = 0; mf < 2; mf++)
                        hmma(acc[mf][2*p+j], al[mf], bh + 2*j);
            }
        }
    }

    #pragma unroll
    for (int mf = 0; mf < 2; mf++) {
        int row = m0 + wm*32 + mf*16 + g;
        #pragma unroll
        for (int nf = 0; nf < 8; nf++) {
            int col = n0 + wn*64 + nf*8 + q4*2;
            *(float2*)&out[(size_t)row * ldc + col]       = make_float2(acc[mf][nf][0], acc[mf][nf][1]);
            *(float2*)&out[(size_t)(row + 8) * ldc + col] = make_float2(acc[mf][nf][2], acc[mf][nf][3]);
        }
    }
}

// ---------------- scan pass 1: chunk end states only ----------------
__global__ __launch_bounds__(256) void k_scan1() {
    const int b = blockIdx.x / NCHUNK, c = blockIdx.x % NCHUNK;
    const int n = threadIdx.x;
    const float Ar = g_Ar[n], Ai = g_Ai[n];
    size_t base = ((size_t)b*SEQ + (size_t)c*CHUNK) * 512 + n;
    float hr = 0.f, hi = 0.f;
    #pragma unroll 8
    for (int j = 0; j < CHUNK; j++) {
        float ur = g_u[base], ui = g_u[base + 256];
        float nhr = fmaf(Ar, hr, fmaf(-Ai, hi, ur));
        float nhi = fmaf(Ar, hi, fmaf( Ai, hr, ui));
        hr = nhr; hi = nhi;
        base += 512;
    }
    g_cr[(b*NCHUNK + c)*NST + n] = hr;
    g_ci[(b*NCHUNK + c)*NST + n] = hi;
}

// ---------------- scan pass 2: cross-chunk prefix ----------------
__global__ __launch_bounds__(256) void k_scan2() {
    const int b = blockIdx.x;
    const int n = threadIdx.x;
    const float Ar = g_ALr[n], Ai = g_ALi[n];
    float hr = 0.f, hi = 0.f;
    for (int cb = 0; cb < 4; cb++) {
        float cr[16], ci[16];
        #pragma unroll
        for (int i = 0; i < 16; i++) {
            int idx = (b*NCHUNK + cb*16 + i)*NST + n;
            cr[i] = g_cr[idx]; ci[i] = g_ci[idx];
        }
        #pragma unroll
        for (int i = 0; i < 16; i++) {
            int idx = (b*NCHUNK + cb*16 + i)*NST + n;
            g_pr[idx] = hr; g_pi[idx] = hi;
            float nhr = fmaf(Ar, hr, fmaf(-Ai, hi, cr[i]));
            float nhi = fmaf(Ar, hi, fmaf( Ai, hr, ci[i]));
            hr = nhr; hi = nhi;
        }
    }
}

// ---------------- scan pass 3: full scan with carry, emit h as bf16 hi/lo ----------------
__global__ __launch_bounds__(256) void k_scan3() {
    const int b = blockIdx.x / NCHUNK, c = blockIdx.x % NCHUNK;
    const int n = threadIdx.x;
    const float Ar = g_Ar[n], Ai = g_Ai[n];
    float hr = g_pr[(b*NCHUNK + c)*NST + n];
    float hi = g_pi[(b*NCHUNK + c)*NST + n];
    size_t base = ((size_t)b*SEQ + (size_t)c*CHUNK) * 512 + n;
    #pragma unroll 8
    for (int j = 0; j < CHUNK; j++) {
        float ur = g_u[base], ui = g_u[base + 256];
        float nhr = fmaf(Ar, hr, fmaf(-Ai, hi, ur));
        float nhi = fmaf(Ar, hi, fmaf( Ai, hr, ui));
        hr = nhr; hi = nhi;
        bsplit(hr, g_hh[base],       g_hl[base]);
        bsplit(hi, g_hh[base + 256], g_hl[base + 256]);
        base += 512;
    }
}

// ---------------- launch ----------------
extern "C" void kernel_launch(void* const* d_in, const int* in_sizes, int n_in,
                              void* d_out, int out_size) {
    const float* x   = (const float*)d_in[0];
    const float* llr = (const float*)d_in[1];
    const float* lim = (const float*)d_in[2];
    const float* ldt = (const float*)d_in[3];
    const float* Bm  = (const float*)d_in[4];
    const float* Cr  = (const float*)d_in[5];
    const float* Ci  = (const float*)d_in[6];
    float* out = (float*)d_out;

    cudaFuncSetAttribute(k_gemm, cudaFuncAttributeMaxDynamicSharedMemorySize, GEMM_SMEM);

    bf16 *xh, *xl, *w1h, *w1l, *w2h, *w2l, *hh, *hl;
    float *u;
    cudaGetSymbolAddress((void**)&xh, g_xh);
    cudaGetSymbolAddress((void**)&xl, g_xl);
    cudaGetSymbolAddress((void**)&w1h, g_W1h);
    cudaGetSymbolAddress((void**)&w1l, g_W1l);
    cudaGetSymbolAddress((void**)&w2h, g_W2h);
    cudaGetSymbolAddress((void**)&w2l, g_W2l);
    cudaGetSymbolAddress((void**)&hh, g_hh);
    cudaGetSymbolAddress((void**)&hl, g_hl);
    cudaGetSymbolAddress((void**)&u, g_u);

    k_setup<<<1, 256>>>(llr, lim, ldt);
    k_w1<<<(256*256)/256, 256>>>(Bm);
    k_w2<<<(256*512)/256, 256>>>(Cr, Ci);
    k_cvt<<<(M_TOT*DIN/4)/256, 256>>>(x);
    // GEMM1: u[M,512] = x @ [Bbar_r;Bbar_i]^T
    k_gemm<<<dim3(512/128, M_TOT/MT), 512, GEMM_SMEM>>>(xh, xl, DIN, w1h, w1l, u, 512, DIN);
    k_scan1<<<BT*NCHUNK, 256>>>();
    k_scan2<<<BT, 256>>>();
    k_scan3<<<BT*NCHUNK, 256>>>();
    // GEMM2: out[M,256] = [hr|hi] @ [Cr|-Ci]^T
    k_gemm<<<dim3(DOUT/128, M_TOT/MT), 512, GEMM_SMEM>>>(hh, hl, 512, w2h, w2l, out, DOUT, 512);
}

// round 12
// speedup vs baseline: 1.1987x; 1.1985x over previous
#include <cuda_runtime.h>
#include <cuda_fp16.h>
#include <cstdint>

#define BT 8
#define SEQ 4096
#define NST 256
#define DIN 256
#define DOUT 256
#define M_TOT (BT*SEQ)          // 32768
#define CHUNK 64
#define NCHUNK (SEQ/CHUNK)      // 64

typedef unsigned long long u64;
typedef __half f16;

// ---------------- device scratch ----------------
__device__ float g_Ar[NST], g_Ai[NST];
__device__ float g_ALr[NST], g_ALi[NST];
__device__ float g_wr[NST], g_wi[NST];
__device__ f16   g_xh[(size_t)M_TOT*DIN], g_xl[(size_t)M_TOT*DIN];
__device__ f16   g_W1[512*DIN];                 // [Bbar_r; Bbar_i] fp16
__device__ f16   g_W2[DOUT*512];                // [Cr | -Ci] fp16
__device__ float g_u[(size_t)M_TOT*512];        // u: [:,0:256]=real [:,256:512]=imag
__device__ f16   g_hh[(size_t)M_TOT*512];       // h hi
__device__ f16   g_hl[(size_t)M_TOT*512];       // h lo
__device__ float g_cr[BT*NCHUNK*NST], g_ci[BT*NCHUNK*NST];
__device__ float g_pr[BT*NCHUNK*NST], g_pi[BT*NCHUNK*NST];

__device__ __forceinline__ void hsplit(float v, f16& h, f16& l) {
    h = __float2half_rn(v);
    l = __float2half_rn(v - __half2float(h));
}

// mma.sync m16n8k16 row.col fp16 -> f32 accumulate
__device__ __forceinline__ void hmma(float* d, const uint32_t* a, const uint32_t* b) {
    asm volatile(
        "mma.sync.aligned.m16n8k16.row.col.f32.f16.f16.f32 "
        "{%0,%1,%2,%3}, {%4,%5,%6,%7}, {%8,%9}, {%0,%1,%2,%3};"
        : "+f"(d[0]), "+f"(d[1]), "+f"(d[2]), "+f"(d[3])
        : "r"(a[0]), "r"(a[1]), "r"(a[2]), "r"(a[3]), "r"(b[0]), "r"(b[1]));
}
__device__ __forceinline__ void ldsm_x4(uint32_t* r, uint32_t addr) {
    asm volatile("ldmatrix.sync.aligned.m8n8.x4.shared.b16 {%0,%1,%2,%3}, [%4];"
        : "=r"(r[0]), "=r"(r[1]), "=r"(r[2]), "=r"(r[3]) : "r"(addr));
}
__device__ __forceinline__ void cpa16(uint32_t saddr, const void* g) {
    asm volatile("cp.async.cg.shared.global [%0], [%1], 16;" :: "r"(saddr), "l"(g));
}
__device__ __forceinline__ uint32_t smem_u32(const void* p) {
    uint32_t a;
    asm("{ .reg .u64 t; cvta.to.shared.u64 t, %1; cvt.u32.u64 %0, t; }" : "=r"(a) : "l"(p));
    return a;
}
// swizzled byte offset inside a R x 64 f16 tile
__device__ __forceinline__ uint32_t swz(int row, int g8) {
    return (uint32_t)(row * 64 + ((g8 ^ (row & 7)) * 8)) * 2;
}

// ---------------- setup: per-n scalars only ----------------
__global__ void k_setup(const float* __restrict__ llr, const float* __restrict__ lim,
                        const float* __restrict__ ldt) {
    int n = threadIdx.x;
    float lr = -expf(llr[n]);
    float li = lim[n];
    float dt = expf(ldt[n]);
    dt = fminf(fmaxf(dt, 0.005f), 0.1f);
    float dr = 1.f - 0.5f * dt * lr;
    float di = -0.5f * dt * li;
    float nr = 1.f + 0.5f * dt * lr;
    float ni = 0.5f * dt * li;
    float inv = 1.f / (dr*dr + di*di);
    float Ar = (nr*dr + ni*di) * inv;
    float Ai = (ni*dr - nr*di) * inv;
    g_Ar[n] = Ar; g_Ai[n] = Ai;
    g_wr[n] = dt * dr * inv;
    g_wi[n] = -dt * di * inv;
    float pr = 1.f, pi = 0.f;
    for (int j = 0; j < CHUNK; j++) {
        float t = pr*Ar - pi*Ai;
        pi = pr*Ai + pi*Ar;
        pr = t;
    }
    g_ALr[n] = pr; g_ALi[n] = pi;
}

__global__ __launch_bounds__(256) void k_w1(const float* __restrict__ Bm) {
    int idx = blockIdx.x * blockDim.x + threadIdx.x;   // over 256*256
    int n = idx >> 8, k = idx & 255;
    float b = Bm[idx];
    g_W1[idx]             = __float2half_rn(g_wr[n] * b);
    g_W1[(256+n)*DIN + k] = __float2half_rn(g_wi[n] * b);
}

__global__ void k_w2(const float* __restrict__ Cr, const float* __restrict__ Ci) {
    int idx = blockIdx.x * blockDim.x + threadIdx.x;   // over 256*512
    int d = idx >> 9, k = idx & 511;
    float v = (k < 256) ? Cr[d*256 + k] : -Ci[d*256 + (k - 256)];
    g_W2[idx] = __float2half_rn(v);
}

__global__ __launch_bounds__(256) void k_cvt(const float* __restrict__ x) {
    size_t i = (size_t)(blockIdx.x * blockDim.x + threadIdx.x) * 4;
    float4 v = *(const float4*)&x[i];
    f16 h0,l0,h1,l1,h2,l2,h3,l3;
    hsplit(v.x,h0,l0); hsplit(v.y,h1,l1); hsplit(v.z,h2,l2); hsplit(v.w,h3,l3);
    __half2 hh0={h0,h1}, hh1={h2,h3}, ll0={l0,l1}, ll1={l2,l3};
    *(uint2*)&g_xh[i] = make_uint2(*(uint32_t*)&hh0, *(uint32_t*)&hh1);
    *(uint2*)&g_xl[i] = make_uint2(*(uint32_t*)&ll0, *(uint32_t*)&ll1);
}

// ---------------- HMMA GEMM: 256x128 tile, 8 warps (64x64 per warp), fp16 2-pass ----------------
#define MT 256
#define A_EL (MT*64)
#define W_EL (128*64)
#define STAGE_EL (2*A_EL + W_EL)       // Ah, Al, W
#define GEMM_SMEM (2*STAGE_EL*2)

__global__ __launch_bounds__(256, 1) void k_gemm(
    const f16* __restrict__ Ah, const f16* __restrict__ Al, int lda,
    const f16* __restrict__ W,
    float* __restrict__ out, int ldc, int Kdim)
{
    extern __shared__ f16 smem[];
    const uint32_t sb = smem_u32(smem);
    const int tid = threadIdx.x;
    const int wid = tid >> 5, lane = tid & 31;
    const int m0 = blockIdx.y * MT;
    const int n0 = blockIdx.x * 128;
    const int wm = wid >> 1;            // 0..3 -> 64-row strip
    const int wn = wid & 1;             // 0..1 -> 64 cols
    const int g  = lane >> 2;
    const int q4 = lane & 3;

    float acc[4][8][4];
    #pragma unroll
    for (int i = 0; i < 4; i++)
        #pragma unroll
        for (int j = 0; j < 8; j++)
            #pragma unroll
            for (int r = 0; r < 4; r++) acc[i][j][r] = 0.f;

    const int nchunks = Kdim / 64;

    const int a_row = (lane & 7) + ((lane >> 3) & 1) * 8;
    const int a_g8  = lane >> 4;
    const int w_row = (lane & 7) + ((lane >> 4) & 1) * 8;
    const int w_g8  = (lane >> 3) & 1;

    auto prefetch = [&](int stage, int ch) {
        const int k0 = ch * 64;
        const uint32_t s0 = sb + (uint32_t)stage * STAGE_EL * 2;
        const uint32_t sAh = s0, sAl = s0 + A_EL*2, sW = s0 + 2*A_EL*2;
        #pragma unroll
        for (int i = 0; i < 8; i++) {           // A: 2048 16B vecs, hi+lo
            int v = tid + i * 256;
            int row = v >> 3, q = v & 7;
            uint32_t so = swz(row, q);
            const size_t ga = (size_t)(m0 + row) * lda + k0 + q * 8;
            cpa16(sAh + so, Ah + ga);
            cpa16(sAl + so, Al + ga);
        }
        #pragma unroll
        for (int i = 0; i < 4; i++) {           // W: 1024 vecs
            int v = tid + i * 256;
            int row = v >> 3, q = v & 7;
            uint32_t so = swz(row, q);
            cpa16(sW + so, W + (size_t)(n0 + row) * Kdim + k0 + q * 8);
        }
        asm volatile("cp.async.commit_group;");
    };

    prefetch(0, 0);

    for (int ch = 0; ch < nchunks; ch++) {
        const int st = ch & 1;
        asm volatile("cp.async.wait_group 0;");
        __syncthreads();
        if (ch + 1 < nchunks) prefetch(st ^ 1, ch + 1);

        const uint32_t s0 = sb + (uint32_t)st * STAGE_EL * 2;
        const uint32_t sAh = s0, sAl = s0 + A_EL*2, sW = s0 + 2*A_EL*2;

        #pragma unroll
        for (int ks = 0; ks < 4; ks++) {
            uint32_t ah[4][4], al[4][4];
            #pragma unroll
            for (int mf = 0; mf < 4; mf++) {
                int row = wm*64 + mf*16 + a_row;
                uint32_t off = swz(row, ks*2 + a_g8);
                ldsm_x4(ah[mf], sAh + off);
                ldsm_x4(al[mf], sAl + off);
            }
            #pragma unroll
            for (int p = 0; p < 4; p++) {
                int nrow = wn*64 + p*16 + w_row;
                uint32_t bh[4];
                ldsm_x4(bh, sW + swz(nrow, ks*2 + w_g8));
                #pragma unroll
                for (int j = 0; j < 2; j++)
                    #pragma unroll
                    for (int mf = 0; mf < 4; mf++)
                        hmma(acc[mf][2*p+j], ah[mf], bh + 2*j);
                #pragma unroll
                for (int j = 0; j < 2; j++)
                    #pragma unroll
                    for (int mf = 0; mf < 4; mf++)
                        hmma(acc[mf][2*p+j], al[mf], bh + 2*j);
            }
        }
    }

    #pragma unroll
    for (int mf = 0; mf < 4; mf++) {
        int row = m0 + wm*64 + mf*16 + g;
        #pragma unroll
        for (int nf = 0; nf < 8; nf++) {
            int col = n0 + wn*64 + nf*8 + q4*2;
            *(float2*)&out[(size_t)row * ldc + col]       = make_float2(acc[mf][nf][0], acc[mf][nf][1]);
            *(float2*)&out[(size_t)(row + 8) * ldc + col] = make_float2(acc[mf][nf][2], acc[mf][nf][3]);
        }
    }
}

// ---------------- scan pass 1: chunk end states only ----------------
__global__ __launch_bounds__(256) void k_scan1() {
    const int b = blockIdx.x / NCHUNK, c = blockIdx.x % NCHUNK;
    const int n = threadIdx.x;
    const float Ar = g_Ar[n], Ai = g_Ai[n];
    size_t base = ((size_t)b*SEQ + (size_t)c*CHUNK) * 512 + n;
    float hr = 0.f, hi = 0.f;
    #pragma unroll 8
    for (int j = 0; j < CHUNK; j++) {
        float ur = g_u[base], ui = g_u[base + 256];
        float nhr = fmaf(Ar, hr, fmaf(-Ai, hi, ur));
        float nhi = fmaf(Ar, hi, fmaf( Ai, hr, ui));
        hr = nhr; hi = nhi;
        base += 512;
    }
    g_cr[(b*NCHUNK + c)*NST + n] = hr;
    g_ci[(b*NCHUNK + c)*NST + n] = hi;
}

// ---------------- scan pass 2: cross-chunk prefix ----------------
__global__ __launch_bounds__(256) void k_scan2() {
    const int b = blockIdx.x;
    const int n = threadIdx.x;
    const float Ar = g_ALr[n], Ai = g_ALi[n];
    float hr = 0.f, hi = 0.f;
    for (int cb = 0; cb < 4; cb++) {
        float cr[16], ci[16];
        #pragma unroll
        for (int i = 0; i < 16; i++) {
            int idx = (b*NCHUNK + cb*16 + i)*NST + n;
            cr[i] = g_cr[idx]; ci[i] = g_ci[idx];
        }
        #pragma unroll
        for (int i = 0; i < 16; i++) {
            int idx = (b*NCHUNK + cb*16 + i)*NST + n;
            g_pr[idx] = hr; g_pi[idx] = hi;
            float nhr = fmaf(Ar, hr, fmaf(-Ai, hi, cr[i]));
            float nhi = fmaf(Ar, hi, fmaf( Ai, hr, ci[i]));
            hr = nhr; hi = nhi;
        }
    }
}

// ---------------- scan pass 3: full scan with carry, emit h as fp16 hi/lo ----------------
__global__ __launch_bounds__(256) void k_scan3() {
    const int b = blockIdx.x / NCHUNK, c = blockIdx.x % NCHUNK;
    const int n = threadIdx.x;
    const float Ar = g_Ar[n], Ai = g_Ai[n];
    float hr = g_pr[(b*NCHUNK + c)*NST + n];
    float hi = g_pi[(b*NCHUNK + c)*NST + n];
    size_t base = ((size_t)b*SEQ + (size_t)c*CHUNK) * 512 + n;
    #pragma unroll 8
    for (int j = 0; j < CHUNK; j++) {
        float ur = g_u[base], ui = g_u[base + 256];
        float nhr = fmaf(Ar, hr, fmaf(-Ai, hi, ur));
        float nhi = fmaf(Ar, hi, fmaf( Ai, hr, ui));
        hr = nhr; hi = nhi;
        hsplit(hr, g_hh[base],       g_hl[base]);
        hsplit(hi, g_hh[base + 256], g_hl[base + 256]);
        base += 512;
    }
}

// ---------------- launch ----------------
extern "C" void kernel_launch(void* const* d_in, const int* in_sizes, int n_in,
                              void* d_out, int out_size) {
    const float* x   = (const float*)d_in[0];
    const float* llr = (const float*)d_in[1];
    const float* lim = (const float*)d_in[2];
    const float* ldt = (const float*)d_in[3];
    const float* Bm  = (const float*)d_in[4];
    const float* Cr  = (const float*)d_in[5];
    const float* Ci  = (const float*)d_in[6];
    float* out = (float*)d_out;

    cudaFuncSetAttribute(k_gemm, cudaFuncAttributeMaxDynamicSharedMemorySize, GEMM_SMEM);

    f16 *xh, *xl, *w1, *w2, *hh, *hl;
    float *u;
    cudaGetSymbolAddress((void**)&xh, g_xh);
    cudaGetSymbolAddress((void**)&xl, g_xl);
    cudaGetSymbolAddress((void**)&w1, g_W1);
    cudaGetSymbolAddress((void**)&w2, g_W2);
    cudaGetSymbolAddress((void**)&hh, g_hh);
    cudaGetSymbolAddress((void**)&hl, g_hl);
    cudaGetSymbolAddress((void**)&u, g_u);

    k_setup<<<1, 256>>>(llr, lim, ldt);
    k_w1<<<(256*256)/256, 256>>>(Bm);
    k_w2<<<(256*512)/256, 256>>>(Cr, Ci);
    k_cvt<<<(M_TOT*DIN/4)/256, 256>>>(x);
    // GEMM1: u[M,512] = x @ [Bbar_r;Bbar_i]^T
    k_gemm<<<dim3(512/128, M_TOT/MT), 256, GEMM_SMEM>>>(xh, xl, DIN, w1, u, 512, DIN);
    k_scan1<<<BT*NCHUNK, 256>>>();
    k_scan2<<<BT, 256>>>();
    k_scan3<<<BT*NCHUNK, 256>>>();
    // GEMM2: out[M,256] = [hr|hi] @ [Cr|-Ci]^T
    k_gemm<<<dim3(DOUT/128, M_TOT/MT), 256, GEMM_SMEM>>>(hh, hl, 512, w2, out, DOUT, 512);
}

// round 13
// speedup vs baseline: 1.6467x; 1.3738x over previous
#include <cuda_runtime.h>
#include <cuda_fp16.h>
#include <cstdint>

#define BT 8
#define SEQ 4096
#define NST 256
#define DIN 256
#define DOUT 256
#define M_TOT (BT*SEQ)          // 32768
#define CHUNK 64
#define NCHUNK (SEQ/CHUNK)      // 64

typedef unsigned long long u64;
typedef __half f16;

// ---------------- device scratch ----------------
__device__ float g_Ar[NST], g_Ai[NST];
__device__ float g_ALr[NST], g_ALi[NST];
__device__ float g_wr[NST], g_wi[NST];
__device__ f16   g_x16[(size_t)M_TOT*DIN];
__device__ f16   g_W1[512*DIN];                 // [Bbar_r; Bbar_i] fp16
__device__ f16   g_W2[DOUT*512];                // [Cr | -Ci] fp16
__device__ float g_u[(size_t)M_TOT*512];        // u: [:,0:256]=real [:,256:512]=imag
__device__ f16   g_h16[(size_t)M_TOT*512];      // h fp16
__device__ float g_cr[BT*NCHUNK*NST], g_ci[BT*NCHUNK*NST];
__device__ float g_pr[BT*NCHUNK*NST], g_pi[BT*NCHUNK*NST];

// mma.sync m16n8k16 row.col fp16 -> f32 accumulate
__device__ __forceinline__ void hmma(float* d, const uint32_t* a, const uint32_t* b) {
    asm volatile(
        "mma.sync.aligned.m16n8k16.row.col.f32.f16.f16.f32 "
        "{%0,%1,%2,%3}, {%4,%5,%6,%7}, {%8,%9}, {%0,%1,%2,%3};"
        : "+f"(d[0]), "+f"(d[1]), "+f"(d[2]), "+f"(d[3])
        : "r"(a[0]), "r"(a[1]), "r"(a[2]), "r"(a[3]), "r"(b[0]), "r"(b[1]));
}
__device__ __forceinline__ void ldsm_x4(uint32_t* r, uint32_t addr) {
    asm volatile("ldmatrix.sync.aligned.m8n8.x4.shared.b16 {%0,%1,%2,%3}, [%4];"
        : "=r"(r[0]), "=r"(r[1]), "=r"(r[2]), "=r"(r[3]) : "r"(addr));
}
__device__ __forceinline__ void cpa16(uint32_t saddr, const void* g) {
    asm volatile("cp.async.cg.shared.global [%0], [%1], 16;" :: "r"(saddr), "l"(g));
}
__device__ __forceinline__ uint32_t smem_u32(const void* p) {
    uint32_t a;
    asm("{ .reg .u64 t; cvta.to.shared.u64 t, %1; cvt.u32.u64 %0, t; }" : "=r"(a) : "l"(p));
    return a;
}
// swizzled byte offset inside a R x 64 f16 tile
__device__ __forceinline__ uint32_t swz(int row, int g8) {
    return (uint32_t)(row * 64 + ((g8 ^ (row & 7)) * 8)) * 2;
}

// ---------------- setup: per-n scalars only ----------------
__global__ void k_setup(const float* __restrict__ llr, const float* __restrict__ lim,
                        const float* __restrict__ ldt) {
    int n = threadIdx.x;
    float lr = -expf(llr[n]);
    float li = lim[n];
    float dt = expf(ldt[n]);
    dt = fminf(fmaxf(dt, 0.005f), 0.1f);
    float dr = 1.f - 0.5f * dt * lr;
    float di = -0.5f * dt * li;
    float nr = 1.f + 0.5f * dt * lr;
    float ni = 0.5f * dt * li;
    float inv = 1.f / (dr*dr + di*di);
    float Ar = (nr*dr + ni*di) * inv;
    float Ai = (ni*dr - nr*di) * inv;
    g_Ar[n] = Ar; g_Ai[n] = Ai;
    g_wr[n] = dt * dr * inv;
    g_wi[n] = -dt * di * inv;
    float pr = 1.f, pi = 0.f;
    for (int j = 0; j < CHUNK; j++) {
        float t = pr*Ar - pi*Ai;
        pi = pr*Ai + pi*Ar;
        pr = t;
    }
    g_ALr[n] = pr; g_ALi[n] = pi;
}

__global__ __launch_bounds__(256) void k_w1(const float* __restrict__ Bm) {
    int idx = blockIdx.x * blockDim.x + threadIdx.x;   // over 256*256
    int n = idx >> 8, k = idx & 255;
    float b = Bm[idx];
    g_W1[idx]             = __float2half_rn(g_wr[n] * b);
    g_W1[(256+n)*DIN + k] = __float2half_rn(g_wi[n] * b);
}

__global__ void k_w2(const float* __restrict__ Cr, const float* __restrict__ Ci) {
    int idx = blockIdx.x * blockDim.x + threadIdx.x;   // over 256*512
    int d = idx >> 9, k = idx & 511;
    float v = (k < 256) ? Cr[d*256 + k] : -Ci[d*256 + (k - 256)];
    g_W2[idx] = __float2half_rn(v);
}

__global__ __launch_bounds__(256) void k_cvt(const float* __restrict__ x) {
    size_t i = (size_t)(blockIdx.x * blockDim.x + threadIdx.x) * 4;
    float4 v = *(const float4*)&x[i];
    __half2 a = {__float2half_rn(v.x), __float2half_rn(v.y)};
    __half2 b = {__float2half_rn(v.z), __float2half_rn(v.w)};
    *(uint2*)&g_x16[i] = make_uint2(*(uint32_t*)&a, *(uint32_t*)&b);
}

// ---------------- HMMA GEMM: 256x128 tile, 8 warps (64x64 per warp), fp16 single-pass ----------------
#define MT 256
#define A_EL (MT*64)
#define W_EL (128*64)
#define STAGE_EL (A_EL + W_EL)
#define GEMM_SMEM (2*STAGE_EL*2)

__global__ __launch_bounds__(256, 1) void k_gemm(
    const f16* __restrict__ A, int lda,
    const f16* __restrict__ W,
    float* __restrict__ out, int ldc, int Kdim)
{
    extern __shared__ f16 smem[];
    const uint32_t sb = smem_u32(smem);
    const int tid = threadIdx.x;
    const int wid = tid >> 5, lane = tid & 31;
    const int m0 = blockIdx.y * MT;
    const int n0 = blockIdx.x * 128;
    const int wm = wid >> 1;            // 0..3 -> 64-row strip
    const int wn = wid & 1;             // 0..1 -> 64 cols
    const int g  = lane >> 2;
    const int q4 = lane & 3;

    float acc[4][8][4];
    #pragma unroll
    for (int i = 0; i < 4; i++)
        #pragma unroll
        for (int j = 0; j < 8; j++)
            #pragma unroll
            for (int r = 0; r < 4; r++) acc[i][j][r] = 0.f;

    const int nchunks = Kdim / 64;

    const int a_row = (lane & 7) + ((lane >> 3) & 1) * 8;
    const int a_g8  = lane >> 4;
    const int w_row = (lane & 7) + ((lane >> 4) & 1) * 8;
    const int w_g8  = (lane >> 3) & 1;

    auto prefetch = [&](int stage, int ch) {
        const int k0 = ch * 64;
        const uint32_t s0 = sb + (uint32_t)stage * STAGE_EL * 2;
        const uint32_t sA = s0, sW = s0 + A_EL*2;
        #pragma unroll
        for (int i = 0; i < 8; i++) {           // A: 2048 16B vecs
            int v = tid + i * 256;
            int row = v >> 3, q = v & 7;
            cpa16(sA + swz(row, q), A + (size_t)(m0 + row) * lda + k0 + q * 8);
        }
        #pragma unroll
        for (int i = 0; i < 4; i++) {           // W: 1024 vecs
            int v = tid + i * 256;
            int row = v >> 3, q = v & 7;
            cpa16(sW + swz(row, q), W + (size_t)(n0 + row) * Kdim + k0 + q * 8);
        }
        asm volatile("cp.async.commit_group;");
    };

    prefetch(0, 0);

    for (int ch = 0; ch < nchunks; ch++) {
        const int st = ch & 1;
        asm volatile("cp.async.wait_group 0;");
        __syncthreads();
        if (ch + 1 < nchunks) prefetch(st ^ 1, ch + 1);

        const uint32_t s0 = sb + (uint32_t)st * STAGE_EL * 2;
        const uint32_t sA = s0, sW = s0 + A_EL*2;

        #pragma unroll
        for (int ks = 0; ks < 4; ks++) {
            uint32_t ah[4][4];
            #pragma unroll
            for (int mf = 0; mf < 4; mf++) {
                int row = wm*64 + mf*16 + a_row;
                ldsm_x4(ah[mf], sA + swz(row, ks*2 + a_g8));
            }
            #pragma unroll
            for (int p = 0; p < 4; p++) {
                int nrow = wn*64 + p*16 + w_row;
                uint32_t bh[4];
                ldsm_x4(bh, sW + swz(nrow, ks*2 + w_g8));
                #pragma unroll
                for (int j = 0; j < 2; j++)
                    #pragma unroll
                    for (int mf = 0; mf < 4; mf++)
                        hmma(acc[mf][2*p+j], ah[mf], bh + 2*j);
            }
        }
    }

    #pragma unroll
    for (int mf = 0; mf < 4; mf++) {
        int row = m0 + wm*64 + mf*16 + g;
        #pragma unroll
        for (int nf = 0; nf < 8; nf++) {
            int col = n0 + wn*64 + nf*8 + q4*2;
            *(float2*)&out[(size_t)row * ldc + col]       = make_float2(acc[mf][nf][0], acc[mf][nf][1]);
            *(float2*)&out[(size_t)(row + 8) * ldc + col] = make_float2(acc[mf][nf][2], acc[mf][nf][3]);
        }
    }
}

// ---------------- scan pass 1: chunk end states only ----------------
__global__ __launch_bounds__(256) void k_scan1() {
    const int b = blockIdx.x / NCHUNK, c = blockIdx.x % NCHUNK;
    const int n = threadIdx.x;
    const float Ar = g_Ar[n], Ai = g_Ai[n];
    size_t base = ((size_t)b*SEQ + (size_t)c*CHUNK) * 512 + n;
    float hr = 0.f, hi = 0.f;
    #pragma unroll 8
    for (int j = 0; j < CHUNK; j++) {
        float ur = g_u[base], ui = g_u[base + 256];
        float nhr = fmaf(Ar, hr, fmaf(-Ai, hi, ur));
        float nhi = fmaf(Ar, hi, fmaf( Ai, hr, ui));
        hr = nhr; hi = nhi;
        base += 512;
    }
    g_cr[(b*NCHUNK + c)*NST + n] = hr;
    g_ci[(b*NCHUNK + c)*NST + n] = hi;
}

// ---------------- scan pass 2: cross-chunk prefix ----------------
__global__ __launch_bounds__(256) void k_scan2() {
    const int b = blockIdx.x;
    const int n = threadIdx.x;
    const float Ar = g_ALr[n], Ai = g_ALi[n];
    float hr = 0.f, hi = 0.f;
    for (int cb = 0; cb < 4; cb++) {
        float cr[16], ci[16];
        #pragma unroll
        for (int i = 0; i < 16; i++) {
            int idx = (b*NCHUNK + cb*16 + i)*NST + n;
            cr[i] = g_cr[idx]; ci[i] = g_ci[idx];
        }
        #pragma unroll
        for (int i = 0; i < 16; i++) {
            int idx = (b*NCHUNK + cb*16 + i)*NST + n;
            g_pr[idx] = hr; g_pi[idx] = hi;
            float nhr = fmaf(Ar, hr, fmaf(-Ai, hi, cr[i]));
            float nhi = fmaf(Ar, hi, fmaf( Ai, hr, ci[i]));
            hr = nhr; hi = nhi;
        }
    }
}

// ---------------- scan pass 3: full scan with carry, emit h as fp16 ----------------
__global__ __launch_bounds__(256) void k_scan3() {
    const int b = blockIdx.x / NCHUNK, c = blockIdx.x % NCHUNK;
    const int n = threadIdx.x;
    const float Ar = g_Ar[n], Ai = g_Ai[n];
    float hr = g_pr[(b*NCHUNK + c)*NST + n];
    float hi = g_pi[(b*NCHUNK + c)*NST + n];
    size_t base = ((size_t)b*SEQ + (size_t)c*CHUNK) * 512 + n;
    #pragma unroll 8
    for (int j = 0; j < CHUNK; j++) {
        float ur = g_u[base], ui = g_u[base + 256];
        float nhr = fmaf(Ar, hr, fmaf(-Ai, hi, ur));
        float nhi = fmaf(Ar, hi, fmaf( Ai, hr, ui));
        hr = nhr; hi = nhi;
        g_h16[base]       = __float2half_rn(hr);
        g_h16[base + 256] = __float2half_rn(hi);
        base += 512;
    }
}

// ---------------- launch ----------------
extern "C" void kernel_launch(void* const* d_in, const int* in_sizes, int n_in,
                              void* d_out, int out_size) {
    const float* x   = (const float*)d_in[0];
    const float* llr = (const float*)d_in[1];
    const float* lim = (const float*)d_in[2];
    const float* ldt = (const float*)d_in[3];
    const float* Bm  = (const float*)d_in[4];
    const float* Cr  = (const float*)d_in[5];
    const float* Ci  = (const float*)d_in[6];
    float* out = (float*)d_out;

    cudaFuncSetAttribute(k_gemm, cudaFuncAttributeMaxDynamicSharedMemorySize, GEMM_SMEM);

    f16 *x16, *w1, *w2, *h16;
    float *u;
    cudaGetSymbolAddress((void**)&x16, g_x16);
    cudaGetSymbolAddress((void**)&w1, g_W1);
    cudaGetSymbolAddress((void**)&w2, g_W2);
    cudaGetSymbolAddress((void**)&h16, g_h16);
    cudaGetSymbolAddress((void**)&u, g_u);

    k_setup<<<1, 256>>>(llr, lim, ldt);
    k_w1<<<(256*256)/256, 256>>>(Bm);
    k_w2<<<(256*512)/256, 256>>>(Cr, Ci);
    k_cvt<<<(M_TOT*DIN/4)/256, 256>>>(x);
    // GEMM1: u[M,512] = x @ [Bbar_r;Bbar_i]^T
    k_gemm<<<dim3(512/128, M_TOT/MT), 256, GEMM_SMEM>>>(x16, DIN, w1, u, 512, DIN);
    k_scan1<<<BT*NCHUNK, 256>>>();
    k_scan2<<<BT, 256>>>();
    k_scan3<<<BT*NCHUNK, 256>>>();
    // GEMM2: out[M,256] = h @ [Cr|-Ci]^T
    k_gemm<<<dim3(DOUT/128, M_TOT/MT), 256, GEMM_SMEM>>>(h16, 512, w2, out, DOUT, 512);
}

// round 14
// speedup vs baseline: 1.9083x; 1.1589x over previous
#include <cuda_runtime.h>
#include <cuda_fp16.h>
#include <cstdint>

#define BT 8
#define SEQ 4096
#define NST 256
#define DIN 256
#define DOUT 256
#define M_TOT (BT*SEQ)          // 32768
#define CHUNK 64
#define NCHUNK (SEQ/CHUNK)      // 64

typedef unsigned long long u64;
typedef __half f16;

// ---------------- device scratch ----------------
__device__ float g_Ar[NST], g_Ai[NST];
__device__ float g_ALr[NST], g_ALi[NST];
__device__ float g_wr[NST], g_wi[NST];
__device__ f16   g_x16[(size_t)M_TOT*DIN];
__device__ f16   g_W1[512*DIN];                 // [Bbar_r; Bbar_i] fp16
__device__ f16   g_W2[DOUT*512];                // [Cr | -Ci] fp16
__device__ f16   g_u16[(size_t)M_TOT*512];      // u fp16: [:,0:256]=real [:,256:512]=imag
__device__ f16   g_h16[(size_t)M_TOT*512];      // h fp16
__device__ float g_cr[BT*NCHUNK*NST], g_ci[BT*NCHUNK*NST];
__device__ float g_pr[BT*NCHUNK*NST], g_pi[BT*NCHUNK*NST];

// mma.sync m16n8k16 row.col fp16 -> f32 accumulate
__device__ __forceinline__ void hmma(float* d, const uint32_t* a, const uint32_t* b) {
    asm volatile(
        "mma.sync.aligned.m16n8k16.row.col.f32.f16.f16.f32 "
        "{%0,%1,%2,%3}, {%4,%5,%6,%7}, {%8,%9}, {%0,%1,%2,%3};"
        : "+f"(d[0]), "+f"(d[1]), "+f"(d[2]), "+f"(d[3])
        : "r"(a[0]), "r"(a[1]), "r"(a[2]), "r"(a[3]), "r"(b[0]), "r"(b[1]));
}
__device__ __forceinline__ void ldsm_x4(uint32_t* r, uint32_t addr) {
    asm volatile("ldmatrix.sync.aligned.m8n8.x4.shared.b16 {%0,%1,%2,%3}, [%4];"
        : "=r"(r[0]), "=r"(r[1]), "=r"(r[2]), "=r"(r[3]) : "r"(addr));
}
__device__ __forceinline__ void cpa16(uint32_t saddr, const void* g) {
    asm volatile("cp.async.cg.shared.global [%0], [%1], 16;" :: "r"(saddr), "l"(g));
}
__device__ __forceinline__ uint32_t smem_u32(const void* p) {
    uint32_t a;
    asm("{ .reg .u64 t; cvta.to.shared.u64 t, %1; cvt.u32.u64 %0, t; }" : "=r"(a) : "l"(p));
    return a;
}
// swizzled byte offset inside a R x 64 f16 tile
__device__ __forceinline__ uint32_t swz(int row, int g8) {
    return (uint32_t)(row * 64 + ((g8 ^ (row & 7)) * 8)) * 2;
}

// ---------------- setup: per-n scalars only ----------------
__global__ void k_setup(const float* __restrict__ llr, const float* __restrict__ lim,
                        const float* __restrict__ ldt) {
    int n = threadIdx.x;
    float lr = -expf(llr[n]);
    float li = lim[n];
    float dt = expf(ldt[n]);
    dt = fminf(fmaxf(dt, 0.005f), 0.1f);
    float dr = 1.f - 0.5f * dt * lr;
    float di = -0.5f * dt * li;
    float nr = 1.f + 0.5f * dt * lr;
    float ni = 0.5f * dt * li;
    float inv = 1.f / (dr*dr + di*di);
    float Ar = (nr*dr + ni*di) * inv;
    float Ai = (ni*dr - nr*di) * inv;
    g_Ar[n] = Ar; g_Ai[n] = Ai;
    g_wr[n] = dt * dr * inv;
    g_wi[n] = -dt * di * inv;
    float pr = 1.f, pi = 0.f;
    for (int j = 0; j < CHUNK; j++) {
        float t = pr*Ar - pi*Ai;
        pi = pr*Ai + pi*Ar;
        pr = t;
    }
    g_ALr[n] = pr; g_ALi[n] = pi;
}

__global__ __launch_bounds__(256) void k_w1(const float* __restrict__ Bm) {
    int idx = blockIdx.x * blockDim.x + threadIdx.x;   // over 256*256
    int n = idx >> 8, k = idx & 255;
    float b = Bm[idx];
    g_W1[idx]             = __float2half_rn(g_wr[n] * b);
    g_W1[(256+n)*DIN + k] = __float2half_rn(g_wi[n] * b);
}

__global__ void k_w2(const float* __restrict__ Cr, const float* __restrict__ Ci) {
    int idx = blockIdx.x * blockDim.x + threadIdx.x;   // over 256*512
    int d = idx >> 9, k = idx & 511;
    float v = (k < 256) ? Cr[d*256 + k] : -Ci[d*256 + (k - 256)];
    g_W2[idx] = __float2half_rn(v);
}

__global__ __launch_bounds__(256) void k_cvt(const float* __restrict__ x) {
    size_t i = (size_t)(blockIdx.x * blockDim.x + threadIdx.x) * 4;
    float4 v = *(const float4*)&x[i];
    __half2 a = {__float2half_rn(v.x), __float2half_rn(v.y)};
    __half2 b = {__float2half_rn(v.z), __float2half_rn(v.w)};
    *(uint2*)&g_x16[i] = make_uint2(*(uint32_t*)&a, *(uint32_t*)&b);
}

// ---------------- HMMA GEMM: 256x128 tile, 8 warps (64x64 per warp), fp16 single-pass ----------------
// OUT16: write fp16 (half2), else fp32.
#define MT 256
#define A_EL (MT*64)
#define W_EL (128*64)
#define STAGE_EL (A_EL + W_EL)
#define GEMM_SMEM (2*STAGE_EL*2)

template<bool OUT16>
__global__ __launch_bounds__(256, 1) void k_gemm(
    const f16* __restrict__ A, int lda,
    const f16* __restrict__ W,
    void* __restrict__ outv, int ldc, int Kdim)
{
    extern __shared__ f16 smem[];
    const uint32_t sb = smem_u32(smem);
    const int tid = threadIdx.x;
    const int wid = tid >> 5, lane = tid & 31;
    const int m0 = blockIdx.y * MT;
    const int n0 = blockIdx.x * 128;
    const int wm = wid >> 1;            // 0..3 -> 64-row strip
    const int wn = wid & 1;             // 0..1 -> 64 cols
    const int g  = lane >> 2;
    const int q4 = lane & 3;

    float acc[4][8][4];
    #pragma unroll
    for (int i = 0; i < 4; i++)
        #pragma unroll
        for (int j = 0; j < 8; j++)
            #pragma unroll
            for (int r = 0; r < 4; r++) acc[i][j][r] = 0.f;

    const int nchunks = Kdim / 64;

    const int a_row = (lane & 7) + ((lane >> 3) & 1) * 8;
    const int a_g8  = lane >> 4;
    const int w_row = (lane & 7) + ((lane >> 4) & 1) * 8;
    const int w_g8  = (lane >> 3) & 1;

    auto prefetch = [&](int stage, int ch) {
        const int k0 = ch * 64;
        const uint32_t s0 = sb + (uint32_t)stage * STAGE_EL * 2;
        const uint32_t sA = s0, sW = s0 + A_EL*2;
        #pragma unroll
        for (int i = 0; i < 8; i++) {           // A: 2048 16B vecs
            int v = tid + i * 256;
            int row = v >> 3, q = v & 7;
            cpa16(sA + swz(row, q), A + (size_t)(m0 + row) * lda + k0 + q * 8);
        }
        #pragma unroll
        for (int i = 0; i < 4; i++) {           // W: 1024 vecs
            int v = tid + i * 256;
            int row = v >> 3, q = v & 7;
            cpa16(sW + swz(row, q), W + (size_t)(n0 + row) * Kdim + k0 + q * 8);
        }
        asm volatile("cp.async.commit_group;");
    };

    prefetch(0, 0);

    for (int ch = 0; ch < nchunks; ch++) {
        const int st = ch & 1;
        asm volatile("cp.async.wait_group 0;");
        __syncthreads();
        if (ch + 1 < nchunks) prefetch(st ^ 1, ch + 1);

        const uint32_t s0 = sb + (uint32_t)st * STAGE_EL * 2;
        const uint32_t sA = s0, sW = s0 + A_EL*2;

        #pragma unroll
        for (int ks = 0; ks < 4; ks++) {
            uint32_t ah[4][4];
            #pragma unroll
            for (int mf = 0; mf < 4; mf++) {
                int row = wm*64 + mf*16 + a_row;
                ldsm_x4(ah[mf], sA + swz(row, ks*2 + a_g8));
            }
            #pragma unroll
            for (int p = 0; p < 4; p++) {
                int nrow = wn*64 + p*16 + w_row;
                uint32_t bh[4];
                ldsm_x4(bh, sW + swz(nrow, ks*2 + w_g8));
                #pragma unroll
                for (int j = 0; j < 2; j++)
                    #pragma unroll
                    for (int mf = 0; mf < 4; mf++)
                        hmma(acc[mf][2*p+j], ah[mf], bh + 2*j);
            }
        }
    }

    #pragma unroll
    for (int mf = 0; mf < 4; mf++) {
        int row = m0 + wm*64 + mf*16 + g;
        #pragma unroll
        for (int nf = 0; nf < 8; nf++) {
            int col = n0 + wn*64 + nf*8 + q4*2;
            if (OUT16) {
                f16* out = (f16*)outv;
                __half2 v0 = {__float2half_rn(acc[mf][nf][0]), __float2half_rn(acc[mf][nf][1])};
                __half2 v1 = {__float2half_rn(acc[mf][nf][2]), __float2half_rn(acc[mf][nf][3])};
                *(uint32_t*)&out[(size_t)row * ldc + col]       = *(uint32_t*)&v0;
                *(uint32_t*)&out[(size_t)(row + 8) * ldc + col] = *(uint32_t*)&v1;
            } else {
                float* out = (float*)outv;
                *(float2*)&out[(size_t)row * ldc + col]       = make_float2(acc[mf][nf][0], acc[mf][nf][1]);
                *(float2*)&out[(size_t)(row + 8) * ldc + col] = make_float2(acc[mf][nf][2], acc[mf][nf][3]);
            }
        }
    }
}

// ---------------- scan pass 1: chunk end states (128 thr x 2 channels, half2) ----------------
__global__ __launch_bounds__(128) void k_scan1() {
    const int b = blockIdx.x / NCHUNK, c = blockIdx.x % NCHUNK;
    const int t = threadIdx.x;                  // owns n = 2t, 2t+1
    const float2 Ar = {g_Ar[2*t], g_Ar[2*t+1]};
    const float2 Ai = {g_Ai[2*t], g_Ai[2*t+1]};
    size_t base = ((size_t)b*SEQ + (size_t)c*CHUNK) * 512 + 2*t;
    float hr0 = 0.f, hi0 = 0.f, hr1 = 0.f, hi1 = 0.f;
    #pragma unroll 8
    for (int j = 0; j < CHUNK; j++) {
        __half2 ur2 = *(const __half2*)&g_u16[base];
        __half2 ui2 = *(const __half2*)&g_u16[base + 256];
        float2 ur = __half22float2(ur2), ui = __half22float2(ui2);
        float n0r = fmaf(Ar.x, hr0, fmaf(-Ai.x, hi0, ur.x));
        float n0i = fmaf(Ar.x, hi0, fmaf( Ai.x, hr0, ui.x));
        float n1r = fmaf(Ar.y, hr1, fmaf(-Ai.y, hi1, ur.y));
        float n1i = fmaf(Ar.y, hi1, fmaf( Ai.y, hr1, ui.y));
        hr0 = n0r; hi0 = n0i; hr1 = n1r; hi1 = n1i;
        base += 512;
    }
    int idx = (b*NCHUNK + c)*NST + 2*t;
    *(float2*)&g_cr[idx] = make_float2(hr0, hr1);
    *(float2*)&g_ci[idx] = make_float2(hi0, hi1);
}

// ---------------- scan pass 2: cross-chunk prefix ----------------
__global__ __launch_bounds__(256) void k_scan2() {
    const int b = blockIdx.x;
    const int n = threadIdx.x;
    const float Ar = g_ALr[n], Ai = g_ALi[n];
    float hr = 0.f, hi = 0.f;
    for (int cb = 0; cb < 4; cb++) {
        float cr[16], ci[16];
        #pragma unroll
        for (int i = 0; i < 16; i++) {
            int idx = (b*NCHUNK + cb*16 + i)*NST + n;
            cr[i] = g_cr[idx]; ci[i] = g_ci[idx];
        }
        #pragma unroll
        for (int i = 0; i < 16; i++) {
            int idx = (b*NCHUNK + cb*16 + i)*NST + n;
            g_pr[idx] = hr; g_pi[idx] = hi;
            float nhr = fmaf(Ar, hr, fmaf(-Ai, hi, cr[i]));
            float nhi = fmaf(Ar, hi, fmaf( Ai, hr, ci[i]));
            hr = nhr; hi = nhi;
        }
    }
}

// ---------------- scan pass 3: full scan with carry, emit h fp16 (128 thr x 2 ch) ----------------
__global__ __launch_bounds__(128) void k_scan3() {
    const int b = blockIdx.x / NCHUNK, c = blockIdx.x % NCHUNK;
    const int t = threadIdx.x;
    const float2 Ar = {g_Ar[2*t], g_Ar[2*t+1]};
    const float2 Ai = {g_Ai[2*t], g_Ai[2*t+1]};
    int pidx = (b*NCHUNK + c)*NST + 2*t;
    float2 pr = *(const float2*)&g_pr[pidx];
    float2 pi = *(const float2*)&g_pi[pidx];
    float hr0 = pr.x, hi0 = pi.x, hr1 = pr.y, hi1 = pi.y;
    size_t base = ((size_t)b*SEQ + (size_t)c*CHUNK) * 512 + 2*t;
    #pragma unroll 8
    for (int j = 0; j < CHUNK; j++) {
        __half2 ur2 = *(const __half2*)&g_u16[base];
        __half2 ui2 = *(const __half2*)&g_u16[base + 256];
        float2 ur = __half22float2(ur2), ui = __half22float2(ui2);
        float n0r = fmaf(Ar.x, hr0, fmaf(-Ai.x, hi0, ur.x));
        float n0i = fmaf(Ar.x, hi0, fmaf( Ai.x, hr0, ui.x));
        float n1r = fmaf(Ar.y, hr1, fmaf(-Ai.y, hi1, ur.y));
        float n1i = fmaf(Ar.y, hi1, fmaf( Ai.y, hr1, ui.y));
        hr0 = n0r; hi0 = n0i; hr1 = n1r; hi1 = n1i;
        __half2 hrv = {__float2half_rn(hr0), __float2half_rn(hr1)};
        __half2 hiv = {__float2half_rn(hi0), __float2half_rn(hi1)};
        *(uint32_t*)&g_h16[base]       = *(uint32_t*)&hrv;
        *(uint32_t*)&g_h16[base + 256] = *(uint32_t*)&hiv;
        base += 512;
    }
}

// ---------------- launch ----------------
extern "C" void kernel_launch(void* const* d_in, const int* in_sizes, int n_in,
                              void* d_out, int out_size) {
    const float* x   = (const float*)d_in[0];
    const float* llr = (const float*)d_in[1];
    const float* lim = (const float*)d_in[2];
    const float* ldt = (const float*)d_in[3];
    const float* Bm  = (const float*)d_in[4];
    const float* Cr  = (const float*)d_in[5];
    const float* Ci  = (const float*)d_in[6];
    float* out = (float*)d_out;

    cudaFuncSetAttribute(k_gemm<true>,  cudaFuncAttributeMaxDynamicSharedMemorySize, GEMM_SMEM);
    cudaFuncSetAttribute(k_gemm<false>, cudaFuncAttributeMaxDynamicSharedMemorySize, GEMM_SMEM);

    f16 *x16, *w1, *w2, *h16, *u16;
    cudaGetSymbolAddress((void**)&x16, g_x16);
    cudaGetSymbolAddress((void**)&w1, g_W1);
    cudaGetSymbolAddress((void**)&w2, g_W2);
    cudaGetSymbolAddress((void**)&h16, g_h16);
    cudaGetSymbolAddress((void**)&u16, g_u16);

    k_setup<<<1, 256>>>(llr, lim, ldt);
    k_w1<<<(256*256)/256, 256>>>(Bm);
    k_w2<<<(256*512)/256, 256>>>(Cr, Ci);
    k_cvt<<<(M_TOT*DIN/4)/256, 256>>>(x);
    // GEMM1: u16[M,512] = x @ [Bbar_r;Bbar_i]^T   (fp16 output)
    k_gemm<true><<<dim3(512/128, M_TOT/MT), 256, GEMM_SMEM>>>(x16, DIN, w1, u16, 512, DIN);
    k_scan1<<<BT*NCHUNK, 128>>>();
    k_scan2<<<BT, 256>>>();
    k_scan3<<<BT*NCHUNK, 128>>>();
    // GEMM2: out[M,256] = h @ [Cr|-Ci]^T   (fp32 output)
    k_gemm<false><<<dim3(DOUT/128, M_TOT/MT), 256, GEMM_SMEM>>>(h16, 512, w2, out, DOUT, 512);
}

// round 15
// speedup vs baseline: 2.0768x; 1.0883x over previous
#include <cuda_runtime.h>
#include <cuda_fp16.h>
#include <cstdint>

#define BT 8
#define SEQ 4096
#define NST 256
#define DIN 256
#define DOUT 256
#define M_TOT (BT*SEQ)          // 32768
#define CHUNK 64
#define NCHUNK (SEQ/CHUNK)      // 64

typedef unsigned long long u64;
typedef __half f16;

// ---------------- device scratch ----------------
__device__ float g_Ar[NST], g_Ai[NST];
__device__ float g_ALr[NST], g_ALi[NST];
__device__ float g_wr[NST], g_wi[NST];
__device__ f16   g_x16[(size_t)M_TOT*DIN];
__device__ f16   g_W1[512*DIN];                 // [Bbar_r; Bbar_i] fp16
__device__ f16   g_W2[DOUT*512];                // [Cr | -Ci] fp16
__device__ f16   g_u16[(size_t)M_TOT*512];      // u fp16: [:,0:256]=real [:,256:512]=imag
__device__ f16   g_h16[(size_t)M_TOT*512];      // h fp16
__device__ float g_cr[BT*NCHUNK*NST], g_ci[BT*NCHUNK*NST];
__device__ float g_pr[BT*NCHUNK*NST], g_pi[BT*NCHUNK*NST];

// mma.sync m16n8k16 row.col fp16 -> f32 accumulate
__device__ __forceinline__ void hmma(float* d, const uint32_t* a, const uint32_t* b) {
    asm volatile(
        "mma.sync.aligned.m16n8k16.row.col.f32.f16.f16.f32 "
        "{%0,%1,%2,%3}, {%4,%5,%6,%7}, {%8,%9}, {%0,%1,%2,%3};"
        : "+f"(d[0]), "+f"(d[1]), "+f"(d[2]), "+f"(d[3])
        : "r"(a[0]), "r"(a[1]), "r"(a[2]), "r"(a[3]), "r"(b[0]), "r"(b[1]));
}
__device__ __forceinline__ void ldsm_x4(uint32_t* r, uint32_t addr) {
    asm volatile("ldmatrix.sync.aligned.m8n8.x4.shared.b16 {%0,%1,%2,%3}, [%4];"
        : "=r"(r[0]), "=r"(r[1]), "=r"(r[2]), "=r"(r[3]) : "r"(addr));
}
__device__ __forceinline__ void cpa16(uint32_t saddr, const void* g) {
    asm volatile("cp.async.cg.shared.global [%0], [%1], 16;" :: "r"(saddr), "l"(g));
}
__device__ __forceinline__ uint32_t smem_u32(const void* p) {
    uint32_t a;
    asm("{ .reg .u64 t; cvta.to.shared.u64 t, %1; cvt.u32.u64 %0, t; }" : "=r"(a) : "l"(p));
    return a;
}
// swizzled byte offset inside a R x 64 f16 tile
__device__ __forceinline__ uint32_t swz(int row, int g8) {
    return (uint32_t)(row * 64 + ((g8 ^ (row & 7)) * 8)) * 2;
}

// ---------------- setup: per-n scalars only ----------------
__global__ void k_setup(const float* __restrict__ llr, const float* __restrict__ lim,
                        const float* __restrict__ ldt) {
    int n = threadIdx.x;
    float lr = -expf(llr[n]);
    float li = lim[n];
    float dt = expf(ldt[n]);
    dt = fminf(fmaxf(dt, 0.005f), 0.1f);
    float dr = 1.f - 0.5f * dt * lr;
    float di = -0.5f * dt * li;
    float nr = 1.f + 0.5f * dt * lr;
    float ni = 0.5f * dt * li;
    float inv = 1.f / (dr*dr + di*di);
    float Ar = (nr*dr + ni*di) * inv;
    float Ai = (ni*dr - nr*di) * inv;
    g_Ar[n] = Ar; g_Ai[n] = Ai;
    g_wr[n] = dt * dr * inv;
    g_wi[n] = -dt * di * inv;
    float pr = 1.f, pi = 0.f;
    for (int j = 0; j < CHUNK; j++) {
        float t = pr*Ar - pi*Ai;
        pi = pr*Ai + pi*Ar;
        pr = t;
    }
    g_ALr[n] = pr; g_ALi[n] = pi;
}

__global__ __launch_bounds__(256) void k_w1(const float* __restrict__ Bm) {
    int idx = blockIdx.x * blockDim.x + threadIdx.x;   // over 256*256
    int n = idx >> 8, k = idx & 255;
    float b = Bm[idx];
    g_W1[idx]             = __float2half_rn(g_wr[n] * b);
    g_W1[(256+n)*DIN + k] = __float2half_rn(g_wi[n] * b);
}

__global__ void k_w2(const float* __restrict__ Cr, const float* __restrict__ Ci) {
    int idx = blockIdx.x * blockDim.x + threadIdx.x;   // over 256*512
    int d = idx >> 9, k = idx & 511;
    float v = (k < 256) ? Cr[d*256 + k] : -Ci[d*256 + (k - 256)];
    g_W2[idx] = __float2half_rn(v);
}

__global__ __launch_bounds__(256) void k_cvt(const float* __restrict__ x) {
    size_t i = (size_t)(blockIdx.x * blockDim.x + threadIdx.x) * 4;
    float4 v = *(const float4*)&x[i];
    __half2 a = {__float2half_rn(v.x), __float2half_rn(v.y)};
    __half2 b = {__float2half_rn(v.z), __float2half_rn(v.w)};
    *(uint2*)&g_x16[i] = make_uint2(*(uint32_t*)&a, *(uint32_t*)&b);
}

// ---------------- HMMA GEMM: 128x128 tile, 8 warps (32x64), 2 CTAs/SM ----------------
// OUT16: write fp16 (half2), else fp32.
#define MT 128
#define A_EL (MT*64)
#define W_EL (128*64)
#define STAGE_EL (A_EL + W_EL)
#define GEMM_SMEM (2*STAGE_EL*2)     // 64 KB

template<bool OUT16>
__global__ __launch_bounds__(256, 2) void k_gemm(
    const f16* __restrict__ A, int lda,
    const f16* __restrict__ W,
    void* __restrict__ outv, int ldc, int Kdim)
{
    extern __shared__ f16 smem[];
    const uint32_t sb = smem_u32(smem);
    const int tid = threadIdx.x;
    const int wid = tid >> 5, lane = tid & 31;
    const int m0 = blockIdx.y * MT;
    const int n0 = blockIdx.x * 128;
    const int wm = wid >> 1;            // 0..3 -> 32-row strip
    const int wn = wid & 1;             // 0..1 -> 64 cols
    const int g  = lane >> 2;
    const int q4 = lane & 3;

    float acc[2][8][4];
    #pragma unroll
    for (int i = 0; i < 2; i++)
        #pragma unroll
        for (int j = 0; j < 8; j++)
            #pragma unroll
            for (int r = 0; r < 4; r++) acc[i][j][r] = 0.f;

    const int nchunks = Kdim / 64;

    const int a_row = (lane & 7) + ((lane >> 3) & 1) * 8;
    const int a_g8  = lane >> 4;
    const int w_row = (lane & 7) + ((lane >> 4) & 1) * 8;
    const int w_g8  = (lane >> 3) & 1;

    auto prefetch = [&](int stage, int ch) {
        const int k0 = ch * 64;
        const uint32_t s0 = sb + (uint32_t)stage * STAGE_EL * 2;
        const uint32_t sA = s0, sW = s0 + A_EL*2;
        #pragma unroll
        for (int i = 0; i < 4; i++) {           // A: 1024 16B vecs
            int v = tid + i * 256;
            int row = v >> 3, q = v & 7;
            cpa16(sA + swz(row, q), A + (size_t)(m0 + row) * lda + k0 + q * 8);
        }
        #pragma unroll
        for (int i = 0; i < 4; i++) {           // W: 1024 vecs
            int v = tid + i * 256;
            int row = v >> 3, q = v & 7;
            cpa16(sW + swz(row, q), W + (size_t)(n0 + row) * Kdim + k0 + q * 8);
        }
        asm volatile("cp.async.commit_group;");
    };

    prefetch(0, 0);

    for (int ch = 0; ch < nchunks; ch++) {
        const int st = ch & 1;
        asm volatile("cp.async.wait_group 0;");
        __syncthreads();
        if (ch + 1 < nchunks) prefetch(st ^ 1, ch + 1);

        const uint32_t s0 = sb + (uint32_t)st * STAGE_EL * 2;
        const uint32_t sA = s0, sW = s0 + A_EL*2;

        #pragma unroll
        for (int ks = 0; ks < 4; ks++) {
            uint32_t ah[2][4];
            #pragma unroll
            for (int mf = 0; mf < 2; mf++) {
                int row = wm*32 + mf*16 + a_row;
                ldsm_x4(ah[mf], sA + swz(row, ks*2 + a_g8));
            }
            #pragma unroll
            for (int p = 0; p < 4; p++) {
                int nrow = wn*64 + p*16 + w_row;
                uint32_t bh[4];
                ldsm_x4(bh, sW + swz(nrow, ks*2 + w_g8));
                #pragma unroll
                for (int j = 0; j < 2; j++)
                    #pragma unroll
                    for (int mf = 0; mf < 2; mf++)
                        hmma(acc[mf][2*p+j], ah[mf], bh + 2*j);
            }
        }
    }

    #pragma unroll
    for (int mf = 0; mf < 2; mf++) {
        int row = m0 + wm*32 + mf*16 + g;
        #pragma unroll
        for (int nf = 0; nf < 8; nf++) {
            int col = n0 + wn*64 + nf*8 + q4*2;
            if (OUT16) {
                f16* out = (f16*)outv;
                __half2 v0 = {__float2half_rn(acc[mf][nf][0]), __float2half_rn(acc[mf][nf][1])};
                __half2 v1 = {__float2half_rn(acc[mf][nf][2]), __float2half_rn(acc[mf][nf][3])};
                *(uint32_t*)&out[(size_t)row * ldc + col]       = *(uint32_t*)&v0;
                *(uint32_t*)&out[(size_t)(row + 8) * ldc + col] = *(uint32_t*)&v1;
            } else {
                float* out = (float*)outv;
                *(float2*)&out[(size_t)row * ldc + col]       = make_float2(acc[mf][nf][0], acc[mf][nf][1]);
                *(float2*)&out[(size_t)(row + 8) * ldc + col] = make_float2(acc[mf][nf][2], acc[mf][nf][3]);
            }
        }
    }
}

// ---------------- scan pass 1: chunk end states (128 thr x 2 channels, half2) ----------------
__global__ __launch_bounds__(128) void k_scan1() {
    const int b = blockIdx.x / NCHUNK, c = blockIdx.x % NCHUNK;
    const int t = threadIdx.x;                  // owns n = 2t, 2t+1
    const float2 Ar = {g_Ar[2*t], g_Ar[2*t+1]};
    const float2 Ai = {g_Ai[2*t], g_Ai[2*t+1]};
    size_t base = ((size_t)b*SEQ + (size_t)c*CHUNK) * 512 + 2*t;
    float hr0 = 0.f, hi0 = 0.f, hr1 = 0.f, hi1 = 0.f;
    #pragma unroll 8
    for (int j = 0; j < CHUNK; j++) {
        __half2 ur2 = *(const __half2*)&g_u16[base];
        __half2 ui2 = *(const __half2*)&g_u16[base + 256];
        float2 ur = __half22float2(ur2), ui = __half22float2(ui2);
        float n0r = fmaf(Ar.x, hr0, fmaf(-Ai.x, hi0, ur.x));
        float n0i = fmaf(Ar.x, hi0, fmaf( Ai.x, hr0, ui.x));
        float n1r = fmaf(Ar.y, hr1, fmaf(-Ai.y, hi1, ur.y));
        float n1i = fmaf(Ar.y, hi1, fmaf( Ai.y, hr1, ui.y));
        hr0 = n0r; hi0 = n0i; hr1 = n1r; hi1 = n1i;
        base += 512;
    }
    int idx = (b*NCHUNK + c)*NST + 2*t;
    *(float2*)&g_cr[idx] = make_float2(hr0, hr1);
    *(float2*)&g_ci[idx] = make_float2(hi0, hi1);
}

// ---------------- scan pass 2: cross-chunk prefix ----------------
__global__ __launch_bounds__(256) void k_scan2() {
    const int b = blockIdx.x;
    const int n = threadIdx.x;
    const float Ar = g_ALr[n], Ai = g_ALi[n];
    float hr = 0.f, hi = 0.f;
    for (int cb = 0; cb < 4; cb++) {
        float cr[16], ci[16];
        #pragma unroll
        for (int i = 0; i < 16; i++) {
            int idx = (b*NCHUNK + cb*16 + i)*NST + n;
            cr[i] = g_cr[idx]; ci[i] = g_ci[idx];
        }
        #pragma unroll
        for (int i = 0; i < 16; i++) {
            int idx = (b*NCHUNK + cb*16 + i)*NST + n;
            g_pr[idx] = hr; g_pi[idx] = hi;
            float nhr = fmaf(Ar, hr, fmaf(-Ai, hi, cr[i]));
            float nhi = fmaf(Ar, hi, fmaf( Ai, hr, ci[i]));
            hr = nhr; hi = nhi;
        }
    }
}

// ---------------- scan pass 3: full scan with carry, emit h fp16 (128 thr x 2 ch) ----------------
__global__ __launch_bounds__(128) void k_scan3() {
    const int b = blockIdx.x / NCHUNK, c = blockIdx.x % NCHUNK;
    const int t = threadIdx.x;
    const float2 Ar = {g_Ar[2*t], g_Ar[2*t+1]};
    const float2 Ai = {g_Ai[2*t], g_Ai[2*t+1]};
    int pidx = (b*NCHUNK + c)*NST + 2*t;
    float2 pr = *(const float2*)&g_pr[pidx];
    float2 pi = *(const float2*)&g_pi[pidx];
    float hr0 = pr.x, hi0 = pi.x, hr1 = pr.y, hi1 = pi.y;
    size_t base = ((size_t)b*SEQ + (size_t)c*CHUNK) * 512 + 2*t;
    #pragma unroll 8
    for (int j = 0; j < CHUNK; j++) {
        __half2 ur2 = *(const __half2*)&g_u16[base];
        __half2 ui2 = *(const __half2*)&g_u16[base + 256];
        float2 ur = __half22float2(ur2), ui = __half22float2(ui2);
        float n0r = fmaf(Ar.x, hr0, fmaf(-Ai.x, hi0, ur.x));
        float n0i = fmaf(Ar.x, hi0, fmaf( Ai.x, hr0, ui.x));
        float n1r = fmaf(Ar.y, hr1, fmaf(-Ai.y, hi1, ur.y));
        float n1i = fmaf(Ar.y, hi1, fmaf( Ai.y, hr1, ui.y));
        hr0 = n0r; hi0 = n0i; hr1 = n1r; hi1 = n1i;
        __half2 hrv = {__float2half_rn(hr0), __float2half_rn(hr1)};
        __half2 hiv = {__float2half_rn(hi0), __float2half_rn(hi1)};
        *(uint32_t*)&g_h16[base]       = *(uint32_t*)&hrv;
        *(uint32_t*)&g_h16[base + 256] = *(uint32_t*)&hiv;
        base += 512;
    }
}

// ---------------- launch ----------------
extern "C" void kernel_launch(void* const* d_in, const int* in_sizes, int n_in,
                              void* d_out, int out_size) {
    const float* x   = (const float*)d_in[0];
    const float* llr = (const float*)d_in[1];
    const float* lim = (const float*)d_in[2];
    const float* ldt = (const float*)d_in[3];
    const float* Bm  = (const float*)d_in[4];
    const float* Cr  = (const float*)d_in[5];
    const float* Ci  = (const float*)d_in[6];
    float* out = (float*)d_out;

    cudaFuncSetAttribute(k_gemm<true>,  cudaFuncAttributeMaxDynamicSharedMemorySize, GEMM_SMEM);
    cudaFuncSetAttribute(k_gemm<false>, cudaFuncAttributeMaxDynamicSharedMemorySize, GEMM_SMEM);

    f16 *x16, *w1, *w2, *h16, *u16;
    cudaGetSymbolAddress((void**)&x16, g_x16);
    cudaGetSymbolAddress((void**)&w1, g_W1);
    cudaGetSymbolAddress((void**)&w2, g_W2);
    cudaGetSymbolAddress((void**)&h16, g_h16);
    cudaGetSymbolAddress((void**)&u16, g_u16);

    k_setup<<<1, 256>>>(llr, lim, ldt);
    k_w1<<<(256*256)/256, 256>>>(Bm);
    k_w2<<<(256*512)/256, 256>>>(Cr, Ci);
    k_cvt<<<(M_TOT*DIN/4)/256, 256>>>(x);
    // GEMM1: u16[M,512] = x @ [Bbar_r;Bbar_i]^T   (fp16 output)
    k_gemm<true><<<dim3(512/128, M_TOT/MT), 256, GEMM_SMEM>>>(x16, DIN, w1, u16, 512, DIN);
    k_scan1<<<BT*NCHUNK, 128>>>();
    k_scan2<<<BT, 256>>>();
    k_scan3<<<BT*NCHUNK, 128>>>();
    // GEMM2: out[M,256] = h @ [Cr|-Ci]^T   (fp32 output)
    k_gemm<false><<<dim3(DOUT/128, M_TOT/MT), 256, GEMM_SMEM>>>(h16, 512, w2, out, DOUT, 512);
}